// round 11
// baseline (speedup 1.0000x reference)
#include <cuda_runtime.h>
#include <cuda_fp16.h>
#include <cstdint>

#define BB 4
#define HH 16
#define SSEQ 2048
#define DDIM 128
#define BM 128
#define BN 64
#define NTILES (SSEQ / BN)
#define NTH 256
#define N4PLANE (BB * HH * SSEQ * DDIM / 4)   // uint2 (4 fp16) count per plane

// precomputed single-plane fp16 K and V (row-major, same indexing as inputs)
__device__ uint2 g_kh[N4PLANE], g_vh[N4PLANE];

// smem word layout (uint32 words, each = 2 fp16). Row stride 136 elems = 272 B.
#define QST 136
#define QROWW 68
#define Q_HI_W 0
#define Q_LO_W (128 * QROWW)                   // 8704
#define KBUF_W(buf) (17408 + (buf) * 4352)
#define VBUF_W(buf) (26112 + (buf) * 4352)
#define SMEM_WORDS 34816
#define SMEM_BYTES (SMEM_WORDS * 4)            // 139,264 B

__device__ __forceinline__ uint32_t smem_u32(const void* p) {
    uint32_t a;
    asm("{ .reg .u64 t; cvta.to.shared.u64 t, %1; cvt.u32.u64 %0, t; }" : "=r"(a) : "l"(p));
    return a;
}

__device__ __forceinline__ void mma_f16(float c[4],
                                        uint32_t a0, uint32_t a1, uint32_t a2, uint32_t a3,
                                        uint32_t b0, uint32_t b1)
{
    asm volatile(
        "mma.sync.aligned.m16n8k16.row.col.f32.f16.f16.f32 "
        "{%0,%1,%2,%3}, {%4,%5,%6,%7}, {%8,%9}, {%0,%1,%2,%3};"
        : "+f"(c[0]), "+f"(c[1]), "+f"(c[2]), "+f"(c[3])
        : "r"(a0), "r"(a1), "r"(a2), "r"(a3), "r"(b0), "r"(b1));
}

__device__ __forceinline__ void ldsm4(uint32_t& r0, uint32_t& r1, uint32_t& r2, uint32_t& r3,
                                      uint32_t saddr)
{
    asm volatile("ldmatrix.sync.aligned.m8n8.x4.shared.b16 {%0,%1,%2,%3}, [%4];"
                 : "=r"(r0), "=r"(r1), "=r"(r2), "=r"(r3) : "r"(saddr));
}
__device__ __forceinline__ void ldsm4t(uint32_t& r0, uint32_t& r1, uint32_t& r2, uint32_t& r3,
                                       uint32_t saddr)
{
    asm volatile("ldmatrix.sync.aligned.m8n8.x4.trans.shared.b16 {%0,%1,%2,%3}, [%4];"
                 : "=r"(r0), "=r"(r1), "=r"(r2), "=r"(r3) : "r"(saddr));
}

#define CP16(dst, src) \
    asm volatile("cp.async.cg.shared.global [%0], [%1], 16;" :: "r"(dst), "l"(src))
#define CP_COMMIT() asm volatile("cp.async.commit_group;" ::: "memory")
#define CP_WAIT0()  asm volatile("cp.async.wait_group 0;" ::: "memory")

// fp32 pair -> fp16 hi/lo 2-term split, packed half2 words (x0 in low half)
__device__ __forceinline__ void split2h(float x0, float x1, uint32_t& hi, uint32_t& lo)
{
    __half2 h = __floats2half2_rn(x0, x1);
    float2 hf = __half22float2(h);
    __half2 l = __floats2half2_rn(x0 - hf.x, x1 - hf.y);
    hi = *reinterpret_cast<uint32_t*>(&h);
    lo = *reinterpret_cast<uint32_t*>(&l);
}

// one-time K/V conversion: fp32 -> single fp16 plane each
__global__ __launch_bounds__(256)
void conv_kv(const float4* __restrict__ k, const float4* __restrict__ v)
{
    int i = blockIdx.x * blockDim.x + threadIdx.x;
    if (i >= N4PLANE) return;
    float4 x = k[i];
    __half2 a = __floats2half2_rn(x.x, x.y);
    __half2 b = __floats2half2_rn(x.z, x.w);
    g_kh[i] = make_uint2(*reinterpret_cast<uint32_t*>(&a), *reinterpret_cast<uint32_t*>(&b));
    float4 y = v[i];
    a = __floats2half2_rn(y.x, y.y);
    b = __floats2half2_rn(y.z, y.w);
    g_vh[i] = make_uint2(*reinterpret_cast<uint32_t*>(&a), *reinterpret_cast<uint32_t*>(&b));
}

// async-stage K tile only (phase A): 4 cp.async/thread
__device__ __forceinline__ void cp_tile_k(uint32_t sb, int dstbuf, size_t base_e, int tid)
{
    #pragma unroll
    for (int i = 0; i < 4; i++) {
        int chunk = i * NTH + tid;
        int row = chunk >> 4, c = chunk & 15;
        uint32_t smoff = (uint32_t)(row * 272 + c * 16);
        size_t gb = (base_e + (size_t)row * DDIM + c * 8) * 2;
        CP16(sb + KBUF_W(dstbuf) * 4 + smoff, (const char*)g_kh + gb);
    }
}
// async-stage K+V tile (phase B): 8 cp.async/thread
__device__ __forceinline__ void cp_tile_kv(uint32_t sb, int dstbuf, size_t base_e, int tid)
{
    #pragma unroll
    for (int i = 0; i < 4; i++) {
        int chunk = i * NTH + tid;
        int row = chunk >> 4, c = chunk & 15;
        uint32_t smoff = (uint32_t)(row * 272 + c * 16);
        size_t gb = (base_e + (size_t)row * DDIM + c * 8) * 2;
        CP16(sb + KBUF_W(dstbuf) * 4 + smoff, (const char*)g_kh + gb);
        CP16(sb + VBUF_W(dstbuf) * 4 + smoff, (const char*)g_vh + gb);
    }
}

__global__ __launch_bounds__(NTH, 1)
void attn_mma(const float* __restrict__ q,
              const int*   __restrict__ mask,
              float* __restrict__ out,
              float* __restrict__ attn)
{
    extern __shared__ uint32_t SW[];
    const uint32_t sb = smem_u32(SW);

    const int tid  = threadIdx.x;
    const int lane = tid & 31;
    const int w16  = (tid >> 5) * 16;
    const int g    = lane >> 2;
    const int tg   = lane & 3;

    const int h      = blockIdx.x;
    const int qblock = blockIdx.y;
    const int b      = blockIdx.z;
    const int bh     = b * HH + h;
    const int q0     = qblock * BM;
    const size_t head = (size_t)bh * SSEQ * DDIM;

    // ---- async-stage K tile 0 (phase A needs K only) ----
    cp_tile_k(sb, 0, head, tid);
    CP_COMMIT();

    // ---- stage Q tile (128x128) fp16 hi/lo (2-term split) ----
    {
        const float4* qp4 = (const float4*)(q + head + (size_t)q0 * DDIM);
        #pragma unroll
        for (int it = 0; it < 16; it++) {
            int idx = it * NTH + tid;
            int row = idx >> 5;
            int c4  = (idx & 31) << 2;
            float4 x = qp4[idx];
            uint32_t h0, l0, h1, l1;
            split2h(x.x, x.y, h0, l0);
            split2h(x.z, x.w, h1, l1);
            int w = (row * QST + c4) >> 1;
            *(uint2*)(SW + Q_HI_W + w) = make_uint2(h0, h1);
            *(uint2*)(SW + Q_LO_W + w) = make_uint2(l0, l1);
        }
    }

    // ldmatrix lane-address bases (byte offsets within a tile)
    const uint32_t a_byte  = (uint32_t)(((w16 + (lane & 15)) * QST + ((lane & 16) ? 8 : 0)) * 2);
    const uint32_t qhi_ad  = sb + Q_HI_W * 4 + a_byte;
    const uint32_t qlo_ad  = sb + Q_LO_W * 4 + a_byte;
    const uint32_t bk_byte = (uint32_t)((((lane & 7) + ((lane & 16) ? 8 : 0)) * QST +
                                         ((lane & 8) ? 8 : 0)) * 2);
    const uint32_t bv_byte = (uint32_t)((((lane & 7) + ((lane & 8) ? 8 : 0)) * QST) * 2 +
                                        ((lane & 16) ? 16 : 0));

    const float scale = 0.08838834764831843f;   // 1/sqrt(128)
    const int r0 = q0 + w16 + g;
    const int* m0p = mask + ((size_t)b * SSEQ + r0) * SSEQ;
    const int* m1p = m0p + (size_t)8 * SSEQ;
    float* a0p = attn + ((size_t)bh * SSEQ + r0) * SSEQ;
    float* a1p = a0p + (size_t)8 * SSEQ;

    float rsum0 = 0.f, rsum1 = 0.f;

    CP_WAIT0();
    __syncthreads();

    // ================= PHASE A: rowsums only (1-term Q score) =================
    for (int kb = 0; kb < NTILES; kb++) {
        const int buf = kb & 1;
        const int k0  = kb * BN;
        const bool pf = (kb + 1 < NTILES);

        if (pf) {
            cp_tile_k(sb, buf ^ 1, head + (size_t)(k0 + BN) * DDIM, tid);
            CP_COMMIT();
        }

        int2 mv0[8], mv1[8];
        #pragma unroll
        for (int j = 0; j < 8; j++) {
            const int c = k0 + tg * 2 + j * 8;
            mv0[j] = *(const int2*)(m0p + c);
            mv1[j] = *(const int2*)(m1p + c);
        }

        const uint32_t k_ad = sb + KBUF_W(buf) * 4 + bk_byte;

        float sc[8][4];
        #pragma unroll
        for (int j = 0; j < 8; j++)
            #pragma unroll
            for (int p = 0; p < 4; p++) sc[j][p] = 0.f;

        #pragma unroll
        for (int ks = 0; ks < 8; ks++) {
            uint32_t ah0, ah1, ah2, ah3;
            ldsm4(ah0, ah1, ah2, ah3, qhi_ad + ks * 32);
            uint32_t bf[4][4];
            #pragma unroll
            for (int jp = 0; jp < 4; jp++)
                ldsm4(bf[jp][0], bf[jp][1], bf[jp][2], bf[jp][3],
                      k_ad + ks * 32 + jp * (16 * QST * 2));
            #pragma unroll
            for (int jp = 0; jp < 4; jp++) {
                mma_f16(sc[2 * jp],     ah0, ah1, ah2, ah3, bf[jp][0], bf[jp][1]);
                mma_f16(sc[2 * jp + 1], ah0, ah1, ah2, ah3, bf[jp][2], bf[jp][3]);
            }
        }

        #pragma unroll
        for (int j = 0; j < 8; j++) {
            float e00 = mv0[j].x ? __expf(sc[j][0] * scale) : 0.f;
            float e01 = mv0[j].y ? __expf(sc[j][1] * scale) : 0.f;
            float e10 = mv1[j].x ? __expf(sc[j][2] * scale) : 0.f;
            float e11 = mv1[j].y ? __expf(sc[j][3] * scale) : 0.f;
            rsum0 += e00 + e01;
            rsum1 += e10 + e11;
        }

        if (pf) CP_WAIT0();
        __syncthreads();
    }

    // rowsum butterfly within each 4-lane quad -> inv kept in registers
    rsum0 += __shfl_xor_sync(0xFFFFFFFF, rsum0, 1);
    rsum0 += __shfl_xor_sync(0xFFFFFFFF, rsum0, 2);
    rsum1 += __shfl_xor_sync(0xFFFFFFFF, rsum1, 1);
    rsum1 += __shfl_xor_sync(0xFFFFFFFF, rsum1, 2);
    const float inv0 = 1.0f / rsum0;
    const float inv1 = 1.0f / rsum1;

    // ================= PHASE B: normalized attn write + PV ====================
    cp_tile_kv(sb, 0, head, tid);
    CP_COMMIT();

    float o[16][4];
    #pragma unroll
    for (int jn = 0; jn < 16; jn++)
        #pragma unroll
        for (int p = 0; p < 4; p++) o[jn][p] = 0.f;

    CP_WAIT0();
    __syncthreads();

    for (int kb = 0; kb < NTILES; kb++) {
        const int buf = kb & 1;
        const int k0  = kb * BN;
        const bool pf = (kb + 1 < NTILES);

        if (pf) {
            cp_tile_kv(sb, buf ^ 1, head + (size_t)(k0 + BN) * DDIM, tid);
            CP_COMMIT();
        }

        int2 mv0[8], mv1[8];
        #pragma unroll
        for (int j = 0; j < 8; j++) {
            const int c = k0 + tg * 2 + j * 8;
            mv0[j] = *(const int2*)(m0p + c);
            mv1[j] = *(const int2*)(m1p + c);
        }

        const uint32_t k_ad = sb + KBUF_W(buf) * 4 + bk_byte;
        const uint32_t v_ad = sb + VBUF_W(buf) * 4 + bv_byte;

        // ---- score GEMM: 2-term Q (full attn precision) ----
        float sc[8][4];
        #pragma unroll
        for (int j = 0; j < 8; j++)
            #pragma unroll
            for (int p = 0; p < 4; p++) sc[j][p] = 0.f;

        #pragma unroll
        for (int ks = 0; ks < 8; ks++) {
            uint32_t ah0, ah1, ah2, ah3, al0, al1, al2, al3;
            ldsm4(ah0, ah1, ah2, ah3, qhi_ad + ks * 32);
            ldsm4(al0, al1, al2, al3, qlo_ad + ks * 32);
            uint32_t bf[4][4];
            #pragma unroll
            for (int jp = 0; jp < 4; jp++)
                ldsm4(bf[jp][0], bf[jp][1], bf[jp][2], bf[jp][3],
                      k_ad + ks * 32 + jp * (16 * QST * 2));
            #pragma unroll
            for (int jp = 0; jp < 4; jp++) {
                mma_f16(sc[2 * jp],     ah0, ah1, ah2, ah3, bf[jp][0], bf[jp][1]);
                mma_f16(sc[2 * jp + 1], ah0, ah1, ah2, ah3, bf[jp][2], bf[jp][3]);
            }
            #pragma unroll
            for (int jp = 0; jp < 4; jp++) {
                mma_f16(sc[2 * jp],     al0, al1, al2, al3, bf[jp][0], bf[jp][1]);
                mma_f16(sc[2 * jp + 1], al0, al1, al2, al3, bf[jp][2], bf[jp][3]);
            }
        }

        // ---- epilogue: exp, write NORMALIZED attn, pack unnormalized e ----
        uint32_t eh[16], el[16];
        #pragma unroll
        for (int j = 0; j < 8; j++) {
            const int c = k0 + tg * 2 + j * 8;
            float e00 = mv0[j].x ? __expf(sc[j][0] * scale) : 0.f;
            float e01 = mv0[j].y ? __expf(sc[j][1] * scale) : 0.f;
            float e10 = mv1[j].x ? __expf(sc[j][2] * scale) : 0.f;
            float e11 = mv1[j].y ? __expf(sc[j][3] * scale) : 0.f;
            *(float2*)(a0p + c) = make_float2(e00 * inv0, e01 * inv0);
            *(float2*)(a1p + c) = make_float2(e10 * inv1, e11 * inv1);
            split2h(e00, e01, eh[j * 2], el[j * 2]);
            split2h(e10, e11, eh[j * 2 + 1], el[j * 2 + 1]);
        }

        // ---- PV GEMM: o += (eh+el) V ----
        #pragma unroll
        for (int ks = 0; ks < 4; ks++) {
            uint32_t a0 = eh[ks * 4 + 0], a1 = eh[ks * 4 + 1];
            uint32_t a2 = eh[ks * 4 + 2], a3 = eh[ks * 4 + 3];
            uint32_t c0 = el[ks * 4 + 0], c1 = el[ks * 4 + 1];
            uint32_t c2 = el[ks * 4 + 2], c3 = el[ks * 4 + 3];
            #pragma unroll
            for (int gjn = 0; gjn < 2; gjn++) {
                uint32_t vf[4][4];
                #pragma unroll
                for (int j = 0; j < 4; j++) {
                    int jnp = gjn * 4 + j;
                    ldsm4t(vf[j][0], vf[j][1], vf[j][2], vf[j][3],
                           v_ad + ks * (16 * QST * 2) + jnp * 32);
                }
                #pragma unroll
                for (int j = 0; j < 4; j++) {
                    int jnp = gjn * 4 + j;
                    mma_f16(o[2 * jnp],     a0, a1, a2, a3, vf[j][0], vf[j][1]);
                    mma_f16(o[2 * jnp + 1], a0, a1, a2, a3, vf[j][2], vf[j][3]);
                }
                #pragma unroll
                for (int j = 0; j < 4; j++) {
                    int jnp = gjn * 4 + j;
                    mma_f16(o[2 * jnp],     c0, c1, c2, c3, vf[j][0], vf[j][1]);
                    mma_f16(o[2 * jnp + 1], c0, c1, c2, c3, vf[j][2], vf[j][3]);
                }
            }
        }

        if (pf) CP_WAIT0();
        __syncthreads();
    }

    // ---- normalized out ----
    float* o0p = out + ((size_t)bh * SSEQ + r0) * DDIM;
    float* o1p = o0p + (size_t)8 * DDIM;
    #pragma unroll
    for (int jn = 0; jn < 16; jn++) {
        const int c = jn * 8 + tg * 2;
        *(float2*)(o0p + c) = make_float2(o[jn][0] * inv0, o[jn][1] * inv0);
        *(float2*)(o1p + c) = make_float2(o[jn][2] * inv1, o[jn][3] * inv1);
    }
}

extern "C" void kernel_launch(void* const* d_in, const int* in_sizes, int n_in,
                              void* d_out, int out_size)
{
    const float* q    = (const float*)d_in[0];
    const float* k    = (const float*)d_in[1];
    const float* v    = (const float*)d_in[2];
    const int*   mask = (const int*)d_in[3];

    float* out  = (float*)d_out;
    float* attn = out + (size_t)BB * HH * SSEQ * DDIM;

    // one-time (per launch) K/V fp16 conversion into gmem planes
    conv_kv<<<N4PLANE / 256, 256>>>((const float4*)k, (const float4*)v);

    cudaFuncSetAttribute(attn_mma, cudaFuncAttributeMaxDynamicSharedMemorySize, SMEM_BYTES);
    dim3 grid(HH, SSEQ / BM, BB);       // h fastest: concurrent CTAs share mask + K/V in L2
    attn_mma<<<grid, NTH, SMEM_BYTES>>>(q, mask, out, attn);
}

// round 12
// speedup vs baseline: 1.1857x; 1.1857x over previous
#include <cuda_runtime.h>
#include <cuda_fp16.h>
#include <cstdint>

#define BB 4
#define HH 16
#define SSEQ 2048
#define DDIM 128
#define BM 128
#define BN 64
#define NTILES (SSEQ / BN)
#define NTH 256
#define N4PLANE (BB * HH * SSEQ * DDIM / 4)   // uint2 (4 fp16) count per plane
#define NMB (BB * SSEQ * NTILES)              // packed mask words (uint2 per row-tile)

// precomputed single-plane fp16 K and V (row-major, same indexing as inputs)
__device__ uint2 g_kh[N4PLANE], g_vh[N4PLANE];
// packed mask bits: g_mb[(b*SSEQ + row)*NTILES + kb] = 64 key-bits of that tile
__device__ uint2 g_mb[NMB];

// smem word layout (uint32 words, each = 2 fp16). Row stride 136 elems = 272 B.
#define QST 136
#define QROWW 68
#define Q_HI_W 0
#define Q_LO_W (128 * QROWW)                   // 8704
#define KBUF_W(buf) (17408 + (buf) * 4352)
#define VBUF_W(buf) (26112 + (buf) * 4352)
#define SMEM_WORDS 34816
#define SMEM_BYTES (SMEM_WORDS * 4)            // 139,264 B

__device__ __forceinline__ uint32_t smem_u32(const void* p) {
    uint32_t a;
    asm("{ .reg .u64 t; cvta.to.shared.u64 t, %1; cvt.u32.u64 %0, t; }" : "=r"(a) : "l"(p));
    return a;
}

__device__ __forceinline__ void mma_f16(float c[4],
                                        uint32_t a0, uint32_t a1, uint32_t a2, uint32_t a3,
                                        uint32_t b0, uint32_t b1)
{
    asm volatile(
        "mma.sync.aligned.m16n8k16.row.col.f32.f16.f16.f32 "
        "{%0,%1,%2,%3}, {%4,%5,%6,%7}, {%8,%9}, {%0,%1,%2,%3};"
        : "+f"(c[0]), "+f"(c[1]), "+f"(c[2]), "+f"(c[3])
        : "r"(a0), "r"(a1), "r"(a2), "r"(a3), "r"(b0), "r"(b1));
}

__device__ __forceinline__ void ldsm4(uint32_t& r0, uint32_t& r1, uint32_t& r2, uint32_t& r3,
                                      uint32_t saddr)
{
    asm volatile("ldmatrix.sync.aligned.m8n8.x4.shared.b16 {%0,%1,%2,%3}, [%4];"
                 : "=r"(r0), "=r"(r1), "=r"(r2), "=r"(r3) : "r"(saddr));
}
__device__ __forceinline__ void ldsm4t(uint32_t& r0, uint32_t& r1, uint32_t& r2, uint32_t& r3,
                                       uint32_t saddr)
{
    asm volatile("ldmatrix.sync.aligned.m8n8.x4.trans.shared.b16 {%0,%1,%2,%3}, [%4];"
                 : "=r"(r0), "=r"(r1), "=r"(r2), "=r"(r3) : "r"(saddr));
}

#define CP16(dst, src) \
    asm volatile("cp.async.cg.shared.global [%0], [%1], 16;" :: "r"(dst), "l"(src))
#define CP_COMMIT() asm volatile("cp.async.commit_group;" ::: "memory")
#define CP_WAIT0()  asm volatile("cp.async.wait_group 0;" ::: "memory")

// fp32 pair -> fp16 hi/lo 2-term split, packed half2 words (x0 in low half)
__device__ __forceinline__ void split2h(float x0, float x1, uint32_t& hi, uint32_t& lo)
{
    __half2 h = __floats2half2_rn(x0, x1);
    float2 hf = __half22float2(h);
    __half2 l = __floats2half2_rn(x0 - hf.x, x1 - hf.y);
    hi = *reinterpret_cast<uint32_t*>(&h);
    lo = *reinterpret_cast<uint32_t*>(&l);
}
__device__ __forceinline__ uint32_t pack_h2(float x0, float x1)
{
    __half2 h = __floats2half2_rn(x0, x1);
    return *reinterpret_cast<uint32_t*>(&h);
}

// one-time K/V conversion: fp32 -> single fp16 plane each
__global__ __launch_bounds__(256)
void conv_kv(const float4* __restrict__ k, const float4* __restrict__ v)
{
    int i = blockIdx.x * blockDim.x + threadIdx.x;
    if (i >= N4PLANE) return;
    float4 x = k[i];
    __half2 a = __floats2half2_rn(x.x, x.y);
    __half2 b = __floats2half2_rn(x.z, x.w);
    g_kh[i] = make_uint2(*reinterpret_cast<uint32_t*>(&a), *reinterpret_cast<uint32_t*>(&b));
    float4 y = v[i];
    a = __floats2half2_rn(y.x, y.y);
    b = __floats2half2_rn(y.z, y.w);
    g_vh[i] = make_uint2(*reinterpret_cast<uint32_t*>(&a), *reinterpret_cast<uint32_t*>(&b));
}

// one-time mask packing: 64 int32 -> 64 bits (uint2) per (b,row,ktile)
__global__ __launch_bounds__(256)
void conv_mask(const int* __restrict__ mask)
{
    int t = blockIdx.x * blockDim.x + threadIdx.x;
    if (t >= NMB) return;
    int kb   = t & (NTILES - 1);
    int brow = t >> 5;                         // b*SSEQ + row
    const int4* src = (const int4*)(mask + (size_t)brow * SSEQ + kb * BN);
    uint32_t lo = 0, hi = 0;
    #pragma unroll
    for (int i = 0; i < 8; i++) {
        int4 m = src[i];
        uint32_t bits = (m.x ? 1u : 0u) | (m.y ? 2u : 0u) | (m.z ? 4u : 0u) | (m.w ? 8u : 0u);
        if (i < 8 / 2 * 2) {}                  // keep compiler calm
        if (i * 4 < 32) lo |= bits << (i * 4); else hi |= bits << (i * 4 - 32);
    }
    #pragma unroll
    for (int i = 8; i < 16; i++) {
        int4 m = src[i];
        uint32_t bits = (m.x ? 1u : 0u) | (m.y ? 2u : 0u) | (m.z ? 4u : 0u) | (m.w ? 8u : 0u);
        hi |= bits << (i * 4 - 32);
    }
    g_mb[t] = make_uint2(lo, hi);
}

// async-stage K tile only (phase A): 4 cp.async/thread
__device__ __forceinline__ void cp_tile_k(uint32_t sb, int dstbuf, size_t base_e, int tid)
{
    #pragma unroll
    for (int i = 0; i < 4; i++) {
        int chunk = i * NTH + tid;
        int row = chunk >> 4, c = chunk & 15;
        uint32_t smoff = (uint32_t)(row * 272 + c * 16);
        size_t gb = (base_e + (size_t)row * DDIM + c * 8) * 2;
        CP16(sb + KBUF_W(dstbuf) * 4 + smoff, (const char*)g_kh + gb);
    }
}
// async-stage K+V tile (phase B): 8 cp.async/thread
__device__ __forceinline__ void cp_tile_kv(uint32_t sb, int dstbuf, size_t base_e, int tid)
{
    #pragma unroll
    for (int i = 0; i < 4; i++) {
        int chunk = i * NTH + tid;
        int row = chunk >> 4, c = chunk & 15;
        uint32_t smoff = (uint32_t)(row * 272 + c * 16);
        size_t gb = (base_e + (size_t)row * DDIM + c * 8) * 2;
        CP16(sb + KBUF_W(dstbuf) * 4 + smoff, (const char*)g_kh + gb);
        CP16(sb + VBUF_W(dstbuf) * 4 + smoff, (const char*)g_vh + gb);
    }
}

__global__ __launch_bounds__(NTH, 1)
void attn_mma(const float* __restrict__ q,
              float* __restrict__ out,
              float* __restrict__ attn)
{
    extern __shared__ uint32_t SW[];
    const uint32_t sb = smem_u32(SW);

    const int tid  = threadIdx.x;
    const int lane = tid & 31;
    const int w16  = (tid >> 5) * 16;
    const int g    = lane >> 2;
    const int tg   = lane & 3;

    const int h      = blockIdx.x;
    const int qblock = blockIdx.y;
    const int b      = blockIdx.z;
    const int bh     = b * HH + h;
    const int q0     = qblock * BM;
    const size_t head = (size_t)bh * SSEQ * DDIM;

    // ---- async-stage K tile 0 (phase A needs K only) ----
    cp_tile_k(sb, 0, head, tid);
    CP_COMMIT();

    // ---- stage Q tile (128x128) fp16 hi/lo (2-term split) ----
    {
        const float4* qp4 = (const float4*)(q + head + (size_t)q0 * DDIM);
        #pragma unroll
        for (int it = 0; it < 16; it++) {
            int idx = it * NTH + tid;
            int row = idx >> 5;
            int c4  = (idx & 31) << 2;
            float4 x = qp4[idx];
            uint32_t h0, l0, h1, l1;
            split2h(x.x, x.y, h0, l0);
            split2h(x.z, x.w, h1, l1);
            int w = (row * QST + c4) >> 1;
            *(uint2*)(SW + Q_HI_W + w) = make_uint2(h0, h1);
            *(uint2*)(SW + Q_LO_W + w) = make_uint2(l0, l1);
        }
    }

    // ldmatrix lane-address bases (byte offsets within a tile)
    const uint32_t a_byte  = (uint32_t)(((w16 + (lane & 15)) * QST + ((lane & 16) ? 8 : 0)) * 2);
    const uint32_t qhi_ad  = sb + Q_HI_W * 4 + a_byte;
    const uint32_t qlo_ad  = sb + Q_LO_W * 4 + a_byte;
    const uint32_t bk_byte = (uint32_t)((((lane & 7) + ((lane & 16) ? 8 : 0)) * QST +
                                         ((lane & 8) ? 8 : 0)) * 2);
    const uint32_t bv_byte = (uint32_t)((((lane & 7) + ((lane & 8) ? 8 : 0)) * QST) * 2 +
                                        ((lane & 16) ? 16 : 0));

    const float scale = 0.08838834764831843f;   // 1/sqrt(128)
    const int r0 = q0 + w16 + g;
    const uint2* mbp = g_mb + ((size_t)b * SSEQ + r0) * NTILES;   // row r0; +8*NTILES for r0+8
    float* a0p = attn + ((size_t)bh * SSEQ + r0) * SSEQ;
    float* a1p = a0p + (size_t)8 * SSEQ;

    float rsum0 = 0.f, rsum1 = 0.f;

    CP_WAIT0();
    __syncthreads();

    // ---- hoist loop-invariant Q-hi A-fragments (phase A needs no Q ldsm) ----
    uint32_t qh[8][4];
    #pragma unroll
    for (int ks = 0; ks < 8; ks++)
        ldsm4(qh[ks][0], qh[ks][1], qh[ks][2], qh[ks][3], qhi_ad + ks * 32);

    // ================= PHASE A: rowsums only (1-term Q score) =================
    for (int kb = 0; kb < NTILES; kb++) {
        const int buf = kb & 1;
        const bool pf = (kb + 1 < NTILES);

        if (pf) {
            cp_tile_k(sb, buf ^ 1, head + (size_t)(kb + 1) * BN * DDIM, tid);
            CP_COMMIT();
        }

        const uint2 mb0 = mbp[kb];
        const uint2 mb1 = mbp[8 * NTILES + kb];

        const uint32_t k_ad = sb + KBUF_W(buf) * 4 + bk_byte;

        float sc[8][4];
        #pragma unroll
        for (int j = 0; j < 8; j++)
            #pragma unroll
            for (int p = 0; p < 4; p++) sc[j][p] = 0.f;

        #pragma unroll
        for (int ks = 0; ks < 8; ks++) {
            uint32_t bf[4][4];
            #pragma unroll
            for (int jp = 0; jp < 4; jp++)
                ldsm4(bf[jp][0], bf[jp][1], bf[jp][2], bf[jp][3],
                      k_ad + ks * 32 + jp * (16 * QST * 2));
            #pragma unroll
            for (int jp = 0; jp < 4; jp++) {
                mma_f16(sc[2 * jp],     qh[ks][0], qh[ks][1], qh[ks][2], qh[ks][3],
                        bf[jp][0], bf[jp][1]);
                mma_f16(sc[2 * jp + 1], qh[ks][0], qh[ks][1], qh[ks][2], qh[ks][3],
                        bf[jp][2], bf[jp][3]);
            }
        }

        #pragma unroll
        for (int j = 0; j < 8; j++) {
            uint32_t w0 = (j < 4) ? mb0.x : mb0.y;
            uint32_t w1 = (j < 4) ? mb1.x : mb1.y;
            int sh = tg * 2 + (j & 3) * 8;
            float e00 = ((w0 >> sh) & 1)       ? __expf(sc[j][0] * scale) : 0.f;
            float e01 = ((w0 >> (sh + 1)) & 1) ? __expf(sc[j][1] * scale) : 0.f;
            float e10 = ((w1 >> sh) & 1)       ? __expf(sc[j][2] * scale) : 0.f;
            float e11 = ((w1 >> (sh + 1)) & 1) ? __expf(sc[j][3] * scale) : 0.f;
            rsum0 += e00 + e01;
            rsum1 += e10 + e11;
        }

        if (pf) CP_WAIT0();
        __syncthreads();
    }

    // rowsum butterfly within each 4-lane quad -> inv kept in registers
    rsum0 += __shfl_xor_sync(0xFFFFFFFF, rsum0, 1);
    rsum0 += __shfl_xor_sync(0xFFFFFFFF, rsum0, 2);
    rsum1 += __shfl_xor_sync(0xFFFFFFFF, rsum1, 1);
    rsum1 += __shfl_xor_sync(0xFFFFFFFF, rsum1, 2);
    const float inv0 = 1.0f / rsum0;
    const float inv1 = 1.0f / rsum1;

    // ================= PHASE B: normalized attn write + PV ====================
    cp_tile_kv(sb, 0, head, tid);
    CP_COMMIT();

    float o[16][4];
    #pragma unroll
    for (int jn = 0; jn < 16; jn++)
        #pragma unroll
        for (int p = 0; p < 4; p++) o[jn][p] = 0.f;

    CP_WAIT0();
    __syncthreads();

    for (int kb = 0; kb < NTILES; kb++) {
        const int buf = kb & 1;
        const int k0  = kb * BN;
        const bool pf = (kb + 1 < NTILES);

        if (pf) {
            cp_tile_kv(sb, buf ^ 1, head + (size_t)(k0 + BN) * DDIM, tid);
            CP_COMMIT();
        }

        const uint2 mb0 = mbp[kb];
        const uint2 mb1 = mbp[8 * NTILES + kb];

        const uint32_t k_ad = sb + KBUF_W(buf) * 4 + bk_byte;
        const uint32_t v_ad = sb + VBUF_W(buf) * 4 + bv_byte;

        // ---- score GEMM: 2-term Q (full attn precision) ----
        float sc[8][4];
        #pragma unroll
        for (int j = 0; j < 8; j++)
            #pragma unroll
            for (int p = 0; p < 4; p++) sc[j][p] = 0.f;

        #pragma unroll
        for (int ks = 0; ks < 8; ks++) {
            uint32_t al0, al1, al2, al3;
            ldsm4(al0, al1, al2, al3, qlo_ad + ks * 32);
            uint32_t bf[4][4];
            #pragma unroll
            for (int jp = 0; jp < 4; jp++)
                ldsm4(bf[jp][0], bf[jp][1], bf[jp][2], bf[jp][3],
                      k_ad + ks * 32 + jp * (16 * QST * 2));
            #pragma unroll
            for (int jp = 0; jp < 4; jp++) {
                mma_f16(sc[2 * jp],     qh[ks][0], qh[ks][1], qh[ks][2], qh[ks][3],
                        bf[jp][0], bf[jp][1]);
                mma_f16(sc[2 * jp + 1], qh[ks][0], qh[ks][1], qh[ks][2], qh[ks][3],
                        bf[jp][2], bf[jp][3]);
            }
            #pragma unroll
            for (int jp = 0; jp < 4; jp++) {
                mma_f16(sc[2 * jp],     al0, al1, al2, al3, bf[jp][0], bf[jp][1]);
                mma_f16(sc[2 * jp + 1], al0, al1, al2, al3, bf[jp][2], bf[jp][3]);
            }
        }

        // ---- epilogue: exp, write NORMALIZED attn, pack e (single fp16 term) ----
        uint32_t eh[16];
        #pragma unroll
        for (int j = 0; j < 8; j++) {
            const int c = k0 + tg * 2 + j * 8;
            uint32_t w0 = (j < 4) ? mb0.x : mb0.y;
            uint32_t w1 = (j < 4) ? mb1.x : mb1.y;
            int sh = tg * 2 + (j & 3) * 8;
            float e00 = ((w0 >> sh) & 1)       ? __expf(sc[j][0] * scale) : 0.f;
            float e01 = ((w0 >> (sh + 1)) & 1) ? __expf(sc[j][1] * scale) : 0.f;
            float e10 = ((w1 >> sh) & 1)       ? __expf(sc[j][2] * scale) : 0.f;
            float e11 = ((w1 >> (sh + 1)) & 1) ? __expf(sc[j][3] * scale) : 0.f;
            *(float2*)(a0p + c) = make_float2(e00 * inv0, e01 * inv0);
            *(float2*)(a1p + c) = make_float2(e10 * inv1, e11 * inv1);
            eh[j * 2]     = pack_h2(e00, e01);
            eh[j * 2 + 1] = pack_h2(e10, e11);
        }

        // ---- PV GEMM: o += eh * V (single-term e) ----
        #pragma unroll
        for (int ks = 0; ks < 4; ks++) {
            uint32_t a0 = eh[ks * 4 + 0], a1 = eh[ks * 4 + 1];
            uint32_t a2 = eh[ks * 4 + 2], a3 = eh[ks * 4 + 3];
            #pragma unroll
            for (int gjn = 0; gjn < 2; gjn++) {
                uint32_t vf[4][4];
                #pragma unroll
                for (int j = 0; j < 4; j++) {
                    int jnp = gjn * 4 + j;
                    ldsm4t(vf[j][0], vf[j][1], vf[j][2], vf[j][3],
                           v_ad + ks * (16 * QST * 2) + jnp * 32);
                }
                #pragma unroll
                for (int j = 0; j < 4; j++) {
                    int jnp = gjn * 4 + j;
                    mma_f16(o[2 * jnp],     a0, a1, a2, a3, vf[j][0], vf[j][1]);
                    mma_f16(o[2 * jnp + 1], a0, a1, a2, a3, vf[j][2], vf[j][3]);
                }
            }
        }

        if (pf) CP_WAIT0();
        __syncthreads();
    }

    // ---- normalized out ----
    float* o0p = out + ((size_t)bh * SSEQ + r0) * DDIM;
    float* o1p = o0p + (size_t)8 * DDIM;
    #pragma unroll
    for (int jn = 0; jn < 16; jn++) {
        const int c = jn * 8 + tg * 2;
        *(float2*)(o0p + c) = make_float2(o[jn][0] * inv0, o[jn][1] * inv0);
        *(float2*)(o1p + c) = make_float2(o[jn][2] * inv1, o[jn][3] * inv1);
    }
}

extern "C" void kernel_launch(void* const* d_in, const int* in_sizes, int n_in,
                              void* d_out, int out_size)
{
    const float* q    = (const float*)d_in[0];
    const float* k    = (const float*)d_in[1];
    const float* v    = (const float*)d_in[2];
    const int*   mask = (const int*)d_in[3];

    float* out  = (float*)d_out;
    float* attn = out + (size_t)BB * HH * SSEQ * DDIM;

    // one-time (per launch) precompute: K/V fp16 planes + packed mask bits
    conv_kv<<<N4PLANE / 256, 256>>>((const float4*)k, (const float4*)v);
    conv_mask<<<NMB / 256, 256>>>(mask);

    cudaFuncSetAttribute(attn_mma, cudaFuncAttributeMaxDynamicSharedMemorySize, SMEM_BYTES);
    dim3 grid(HH, SSEQ / BM, BB);       // h fastest: concurrent CTAs share K/V + mask in L2
    attn_mma<<<grid, NTH, SMEM_BYTES>>>(q, out, attn);
}

// round 13
// speedup vs baseline: 1.4410x; 1.2154x over previous
#include <cuda_runtime.h>
#include <cuda_fp16.h>
#include <cstdint>

#define BB 4
#define HH 16
#define SSEQ 2048
#define DDIM 128
#define BM 128
#define BN 64
#define NTILES (SSEQ / BN)
#define NTH 256
#define N4PLANE (BB * HH * SSEQ * DDIM / 4)   // uint2 (4 fp16) count per plane
#define NMB (BB * SSEQ * NTILES)              // packed mask words (uint2 per row-tile)

// precomputed single-plane fp16 K and V (row-major, same indexing as inputs)
__device__ uint2 g_kh[N4PLANE], g_vh[N4PLANE];
// packed mask bits: g_mb[(b*SSEQ + row)*NTILES + kb] = 64 key-bits of that tile
__device__ uint2 g_mb[NMB];

// smem word layout (uint32 words, each = 2 fp16). Row stride 136 elems = 272 B.
#define QST 136
#define QROWW 68
#define Q_HI_W 0
#define KBUF_W(buf) (8704 + (buf) * 4352)
#define VBUF_W(buf) (17408 + (buf) * 4352)
#define SMEM_WORDS 26112
#define SMEM_BYTES (SMEM_WORDS * 4)            // 104,448 B

__device__ __forceinline__ uint32_t smem_u32(const void* p) {
    uint32_t a;
    asm("{ .reg .u64 t; cvta.to.shared.u64 t, %1; cvt.u32.u64 %0, t; }" : "=r"(a) : "l"(p));
    return a;
}

__device__ __forceinline__ void mma_f16(float c[4],
                                        uint32_t a0, uint32_t a1, uint32_t a2, uint32_t a3,
                                        uint32_t b0, uint32_t b1)
{
    asm volatile(
        "mma.sync.aligned.m16n8k16.row.col.f32.f16.f16.f32 "
        "{%0,%1,%2,%3}, {%4,%5,%6,%7}, {%8,%9}, {%0,%1,%2,%3};"
        : "+f"(c[0]), "+f"(c[1]), "+f"(c[2]), "+f"(c[3])
        : "r"(a0), "r"(a1), "r"(a2), "r"(a3), "r"(b0), "r"(b1));
}

__device__ __forceinline__ void ldsm4(uint32_t& r0, uint32_t& r1, uint32_t& r2, uint32_t& r3,
                                      uint32_t saddr)
{
    asm volatile("ldmatrix.sync.aligned.m8n8.x4.shared.b16 {%0,%1,%2,%3}, [%4];"
                 : "=r"(r0), "=r"(r1), "=r"(r2), "=r"(r3) : "r"(saddr));
}
__device__ __forceinline__ void ldsm4t(uint32_t& r0, uint32_t& r1, uint32_t& r2, uint32_t& r3,
                                       uint32_t saddr)
{
    asm volatile("ldmatrix.sync.aligned.m8n8.x4.trans.shared.b16 {%0,%1,%2,%3}, [%4];"
                 : "=r"(r0), "=r"(r1), "=r"(r2), "=r"(r3) : "r"(saddr));
}

#define CP16(dst, src) \
    asm volatile("cp.async.cg.shared.global [%0], [%1], 16;" :: "r"(dst), "l"(src))
#define CP_COMMIT() asm volatile("cp.async.commit_group;" ::: "memory")
#define CP_WAIT0()  asm volatile("cp.async.wait_group 0;" ::: "memory")

__device__ __forceinline__ uint32_t pack_h2(float x0, float x1)
{
    __half2 h = __floats2half2_rn(x0, x1);
    return *reinterpret_cast<uint32_t*>(&h);
}

// one-time K/V conversion: fp32 -> single fp16 plane each
__global__ __launch_bounds__(256)
void conv_kv(const float4* __restrict__ k, const float4* __restrict__ v)
{
    int i = blockIdx.x * blockDim.x + threadIdx.x;
    if (i >= N4PLANE) return;
    float4 x = k[i];
    g_kh[i] = make_uint2(pack_h2(x.x, x.y), pack_h2(x.z, x.w));
    float4 y = v[i];
    g_vh[i] = make_uint2(pack_h2(y.x, y.y), pack_h2(y.z, y.w));
}

// one-time mask packing: 64 int32 -> 64 bits (uint2) per (b,row,ktile)
__global__ __launch_bounds__(256)
void conv_mask(const int* __restrict__ mask)
{
    int t = blockIdx.x * blockDim.x + threadIdx.x;
    if (t >= NMB) return;
    int kb   = t & (NTILES - 1);
    int brow = t >> 5;                         // b*SSEQ + row
    const int4* src = (const int4*)(mask + (size_t)brow * SSEQ + kb * BN);
    uint32_t lo = 0, hi = 0;
    #pragma unroll
    for (int i = 0; i < 8; i++) {
        int4 m = src[i];
        uint32_t bits = (m.x ? 1u : 0u) | (m.y ? 2u : 0u) | (m.z ? 4u : 0u) | (m.w ? 8u : 0u);
        lo |= bits << (i * 4);
    }
    #pragma unroll
    for (int i = 8; i < 16; i++) {
        int4 m = src[i];
        uint32_t bits = (m.x ? 1u : 0u) | (m.y ? 2u : 0u) | (m.z ? 4u : 0u) | (m.w ? 8u : 0u);
        hi |= bits << (i * 4 - 32);
    }
    g_mb[t] = make_uint2(lo, hi);
}

// async-stage K tile only (phase A): 4 cp.async/thread
__device__ __forceinline__ void cp_tile_k(uint32_t sb, int dstbuf, size_t base_e, int tid)
{
    #pragma unroll
    for (int i = 0; i < 4; i++) {
        int chunk = i * NTH + tid;
        int row = chunk >> 4, c = chunk & 15;
        uint32_t smoff = (uint32_t)(row * 272 + c * 16);
        size_t gb = (base_e + (size_t)row * DDIM + c * 8) * 2;
        CP16(sb + KBUF_W(dstbuf) * 4 + smoff, (const char*)g_kh + gb);
    }
}
// async-stage K+V tile (phase B): 8 cp.async/thread
__device__ __forceinline__ void cp_tile_kv(uint32_t sb, int dstbuf, size_t base_e, int tid)
{
    #pragma unroll
    for (int i = 0; i < 4; i++) {
        int chunk = i * NTH + tid;
        int row = chunk >> 4, c = chunk & 15;
        uint32_t smoff = (uint32_t)(row * 272 + c * 16);
        size_t gb = (base_e + (size_t)row * DDIM + c * 8) * 2;
        CP16(sb + KBUF_W(dstbuf) * 4 + smoff, (const char*)g_kh + gb);
        CP16(sb + VBUF_W(dstbuf) * 4 + smoff, (const char*)g_vh + gb);
    }
}

__global__ __launch_bounds__(NTH, 1)
void attn_mma(const float* __restrict__ q,
              float* __restrict__ out,
              float* __restrict__ attn)
{
    extern __shared__ uint32_t SW[];
    const uint32_t sb = smem_u32(SW);

    const int tid  = threadIdx.x;
    const int lane = tid & 31;
    const int w16  = (tid >> 5) * 16;
    const int g    = lane >> 2;
    const int tg   = lane & 3;

    const int h      = blockIdx.x;
    const int qblock = blockIdx.y;
    const int b      = blockIdx.z;
    const int bh     = b * HH + h;
    const int q0     = qblock * BM;
    const size_t head = (size_t)bh * SSEQ * DDIM;

    // ---- async-stage K tile 0 (phase A needs K only) ----
    cp_tile_k(sb, 0, head, tid);
    CP_COMMIT();

    // ---- stage Q tile (128x128) single fp16 plane ----
    {
        const float4* qp4 = (const float4*)(q + head + (size_t)q0 * DDIM);
        #pragma unroll
        for (int it = 0; it < 16; it++) {
            int idx = it * NTH + tid;
            int row = idx >> 5;
            int c4  = (idx & 31) << 2;
            float4 x = qp4[idx];
            int w = (row * QST + c4) >> 1;
            *(uint2*)(SW + Q_HI_W + w) = make_uint2(pack_h2(x.x, x.y), pack_h2(x.z, x.w));
        }
    }

    // ldmatrix lane-address bases (byte offsets within a tile)
    const uint32_t a_byte  = (uint32_t)(((w16 + (lane & 15)) * QST + ((lane & 16) ? 8 : 0)) * 2);
    const uint32_t qhi_ad  = sb + Q_HI_W * 4 + a_byte;
    const uint32_t bk_byte = (uint32_t)((((lane & 7) + ((lane & 16) ? 8 : 0)) * QST +
                                         ((lane & 8) ? 8 : 0)) * 2);
    const uint32_t bv_byte = (uint32_t)((((lane & 7) + ((lane & 8) ? 8 : 0)) * QST) * 2 +
                                        ((lane & 16) ? 16 : 0));

    const float scale = 0.08838834764831843f;   // 1/sqrt(128)
    const int r0 = q0 + w16 + g;
    const uint2* mbp = g_mb + ((size_t)b * SSEQ + r0) * NTILES;   // row r0; +8*NTILES for r0+8
    float* a0p = attn + ((size_t)bh * SSEQ + r0) * SSEQ;
    float* a1p = a0p + (size_t)8 * SSEQ;

    float rsum0 = 0.f, rsum1 = 0.f;

    CP_WAIT0();
    __syncthreads();

    // ---- hoist loop-invariant Q A-fragments (no per-tile Q ldsm at all) ----
    uint32_t qh[8][4];
    #pragma unroll
    for (int ks = 0; ks < 8; ks++)
        ldsm4(qh[ks][0], qh[ks][1], qh[ks][2], qh[ks][3], qhi_ad + ks * 32);

    // ================= PHASE A: rowsums only =================
    for (int kb = 0; kb < NTILES; kb++) {
        const int buf = kb & 1;
        const bool pf = (kb + 1 < NTILES);

        if (pf) {
            cp_tile_k(sb, buf ^ 1, head + (size_t)(kb + 1) * BN * DDIM, tid);
            CP_COMMIT();
        }

        const uint2 mb0 = mbp[kb];
        const uint2 mb1 = mbp[8 * NTILES + kb];

        const uint32_t k_ad = sb + KBUF_W(buf) * 4 + bk_byte;

        float sc[8][4];
        #pragma unroll
        for (int j = 0; j < 8; j++)
            #pragma unroll
            for (int p = 0; p < 4; p++) sc[j][p] = 0.f;

        #pragma unroll
        for (int ks = 0; ks < 8; ks++) {
            uint32_t bf[4][4];
            #pragma unroll
            for (int jp = 0; jp < 4; jp++)
                ldsm4(bf[jp][0], bf[jp][1], bf[jp][2], bf[jp][3],
                      k_ad + ks * 32 + jp * (16 * QST * 2));
            #pragma unroll
            for (int jp = 0; jp < 4; jp++) {
                mma_f16(sc[2 * jp],     qh[ks][0], qh[ks][1], qh[ks][2], qh[ks][3],
                        bf[jp][0], bf[jp][1]);
                mma_f16(sc[2 * jp + 1], qh[ks][0], qh[ks][1], qh[ks][2], qh[ks][3],
                        bf[jp][2], bf[jp][3]);
            }
        }

        #pragma unroll
        for (int j = 0; j < 8; j++) {
            uint32_t w0 = (j < 4) ? mb0.x : mb0.y;
            uint32_t w1 = (j < 4) ? mb1.x : mb1.y;
            int sh = tg * 2 + (j & 3) * 8;
            float e00 = ((w0 >> sh) & 1)       ? __expf(sc[j][0] * scale) : 0.f;
            float e01 = ((w0 >> (sh + 1)) & 1) ? __expf(sc[j][1] * scale) : 0.f;
            float e10 = ((w1 >> sh) & 1)       ? __expf(sc[j][2] * scale) : 0.f;
            float e11 = ((w1 >> (sh + 1)) & 1) ? __expf(sc[j][3] * scale) : 0.f;
            rsum0 += e00 + e01;
            rsum1 += e10 + e11;
        }

        if (pf) CP_WAIT0();
        __syncthreads();
    }

    // rowsum butterfly within each 4-lane quad -> inv kept in registers
    rsum0 += __shfl_xor_sync(0xFFFFFFFF, rsum0, 1);
    rsum0 += __shfl_xor_sync(0xFFFFFFFF, rsum0, 2);
    rsum1 += __shfl_xor_sync(0xFFFFFFFF, rsum1, 1);
    rsum1 += __shfl_xor_sync(0xFFFFFFFF, rsum1, 2);
    const float inv0 = 1.0f / rsum0;
    const float inv1 = 1.0f / rsum1;

    // ================= PHASE B: normalized attn write + PV ====================
    cp_tile_kv(sb, 0, head, tid);
    CP_COMMIT();

    float o[16][4];
    #pragma unroll
    for (int jn = 0; jn < 16; jn++)
        #pragma unroll
        for (int p = 0; p < 4; p++) o[jn][p] = 0.f;

    CP_WAIT0();
    __syncthreads();

    for (int kb = 0; kb < NTILES; kb++) {
        const int buf = kb & 1;
        const int k0  = kb * BN;
        const bool pf = (kb + 1 < NTILES);

        if (pf) {
            cp_tile_kv(sb, buf ^ 1, head + (size_t)(k0 + BN) * DDIM, tid);
            CP_COMMIT();
        }

        const uint2 mb0 = mbp[kb];
        const uint2 mb1 = mbp[8 * NTILES + kb];

        const uint32_t k_ad = sb + KBUF_W(buf) * 4 + bk_byte;
        const uint32_t v_ad = sb + VBUF_W(buf) * 4 + bv_byte;

        // ---- score GEMM (identical numerics to phase A) ----
        float sc[8][4];
        #pragma unroll
        for (int j = 0; j < 8; j++)
            #pragma unroll
            for (int p = 0; p < 4; p++) sc[j][p] = 0.f;

        #pragma unroll
        for (int ks = 0; ks < 8; ks++) {
            uint32_t bf[4][4];
            #pragma unroll
            for (int jp = 0; jp < 4; jp++)
                ldsm4(bf[jp][0], bf[jp][1], bf[jp][2], bf[jp][3],
                      k_ad + ks * 32 + jp * (16 * QST * 2));
            #pragma unroll
            for (int jp = 0; jp < 4; jp++) {
                mma_f16(sc[2 * jp],     qh[ks][0], qh[ks][1], qh[ks][2], qh[ks][3],
                        bf[jp][0], bf[jp][1]);
                mma_f16(sc[2 * jp + 1], qh[ks][0], qh[ks][1], qh[ks][2], qh[ks][3],
                        bf[jp][2], bf[jp][3]);
            }
        }

        // ---- epilogue: exp, write NORMALIZED attn, pack e (single fp16 term) ----
        uint32_t eh[16];
        #pragma unroll
        for (int j = 0; j < 8; j++) {
            const int c = k0 + tg * 2 + j * 8;
            uint32_t w0 = (j < 4) ? mb0.x : mb0.y;
            uint32_t w1 = (j < 4) ? mb1.x : mb1.y;
            int sh = tg * 2 + (j & 3) * 8;
            float e00 = ((w0 >> sh) & 1)       ? __expf(sc[j][0] * scale) : 0.f;
            float e01 = ((w0 >> (sh + 1)) & 1) ? __expf(sc[j][1] * scale) : 0.f;
            float e10 = ((w1 >> sh) & 1)       ? __expf(sc[j][2] * scale) : 0.f;
            float e11 = ((w1 >> (sh + 1)) & 1) ? __expf(sc[j][3] * scale) : 0.f;
            *(float2*)(a0p + c) = make_float2(e00 * inv0, e01 * inv0);
            *(float2*)(a1p + c) = make_float2(e10 * inv1, e11 * inv1);
            eh[j * 2]     = pack_h2(e00, e01);
            eh[j * 2 + 1] = pack_h2(e10, e11);
        }

        // ---- PV GEMM: o += eh * V (single-term e) ----
        #pragma unroll
        for (int ks = 0; ks < 4; ks++) {
            uint32_t a0 = eh[ks * 4 + 0], a1 = eh[ks * 4 + 1];
            uint32_t a2 = eh[ks * 4 + 2], a3 = eh[ks * 4 + 3];
            #pragma unroll
            for (int gjn = 0; gjn < 2; gjn++) {
                uint32_t vf[4][4];
                #pragma unroll
                for (int j = 0; j < 4; j++) {
                    int jnp = gjn * 4 + j;
                    ldsm4t(vf[j][0], vf[j][1], vf[j][2], vf[j][3],
                           v_ad + ks * (16 * QST * 2) + jnp * 32);
                }
                #pragma unroll
                for (int j = 0; j < 4; j++) {
                    int jnp = gjn * 4 + j;
                    mma_f16(o[2 * jnp],     a0, a1, a2, a3, vf[j][0], vf[j][1]);
                    mma_f16(o[2 * jnp + 1], a0, a1, a2, a3, vf[j][2], vf[j][3]);
                }
            }
        }

        if (pf) CP_WAIT0();
        __syncthreads();
    }

    // ---- normalized out ----
    float* o0p = out + ((size_t)bh * SSEQ + r0) * DDIM;
    float* o1p = o0p + (size_t)8 * DDIM;
    #pragma unroll
    for (int jn = 0; jn < 16; jn++) {
        const int c = jn * 8 + tg * 2;
        *(float2*)(o0p + c) = make_float2(o[jn][0] * inv0, o[jn][1] * inv0);
        *(float2*)(o1p + c) = make_float2(o[jn][2] * inv1, o[jn][3] * inv1);
    }
}

extern "C" void kernel_launch(void* const* d_in, const int* in_sizes, int n_in,
                              void* d_out, int out_size)
{
    const float* q    = (const float*)d_in[0];
    const float* k    = (const float*)d_in[1];
    const float* v    = (const float*)d_in[2];
    const int*   mask = (const int*)d_in[3];

    float* out  = (float*)d_out;
    float* attn = out + (size_t)BB * HH * SSEQ * DDIM;

    // one-time (per launch) precompute: K/V fp16 planes + packed mask bits
    conv_kv<<<N4PLANE / 256, 256>>>((const float4*)k, (const float4*)v);
    conv_mask<<<NMB / 256, 256>>>(mask);

    cudaFuncSetAttribute(attn_mma, cudaFuncAttributeMaxDynamicSharedMemorySize, SMEM_BYTES);
    dim3 grid(HH, SSEQ / BM, BB);       // h fastest: concurrent CTAs share K/V + mask in L2
    attn_mma<<<grid, NTH, SMEM_BYTES>>>(q, out, attn);
}

// round 14
// speedup vs baseline: 1.7007x; 1.1802x over previous
#include <cuda_runtime.h>
#include <cuda_fp16.h>
#include <cstdint>

#define BB 4
#define HH 16
#define SSEQ 2048
#define DDIM 128
#define BM 128
#define BN 64
#define NTILES (SSEQ / BN)
#define NTH 256
#define N4PLANE (BB * HH * SSEQ * DDIM / 4)   // uint2 (4 fp16) count per plane
#define NMB (BB * SSEQ * NTILES)              // packed mask words (uint2 per row-tile)

// precomputed single-plane fp16 K and V (row-major, same indexing as inputs)
__device__ uint2 g_kh[N4PLANE], g_vh[N4PLANE];
// packed mask bits: g_mb[(b*SSEQ + row)*NTILES + kb] = 64 key-bits of that tile
__device__ uint2 g_mb[NMB];

// smem word layout (uint32 words, each = 2 fp16). Row stride 136 elems = 272 B.
#define QST 136
#define Q_HI_W 0
#define KBUF_W(b) (8704 + (b) * 4352)          // 2 buffers
#define VBUF_W(b) (17408 + (b) * 4352)         // 3 buffers
#define SMEM_WORDS 30464
#define SMEM_BYTES (SMEM_WORDS * 4)            // 121,856 B

__device__ __forceinline__ uint32_t smem_u32(const void* p) {
    uint32_t a;
    asm("{ .reg .u64 t; cvta.to.shared.u64 t, %1; cvt.u32.u64 %0, t; }" : "=r"(a) : "l"(p));
    return a;
}

__device__ __forceinline__ void mma_f16(float c[4],
                                        uint32_t a0, uint32_t a1, uint32_t a2, uint32_t a3,
                                        uint32_t b0, uint32_t b1)
{
    asm volatile(
        "mma.sync.aligned.m16n8k16.row.col.f32.f16.f16.f32 "
        "{%0,%1,%2,%3}, {%4,%5,%6,%7}, {%8,%9}, {%0,%1,%2,%3};"
        : "+f"(c[0]), "+f"(c[1]), "+f"(c[2]), "+f"(c[3])
        : "r"(a0), "r"(a1), "r"(a2), "r"(a3), "r"(b0), "r"(b1));
}

__device__ __forceinline__ void ldsm4(uint32_t& r0, uint32_t& r1, uint32_t& r2, uint32_t& r3,
                                      uint32_t saddr)
{
    asm volatile("ldmatrix.sync.aligned.m8n8.x4.shared.b16 {%0,%1,%2,%3}, [%4];"
                 : "=r"(r0), "=r"(r1), "=r"(r2), "=r"(r3) : "r"(saddr));
}
__device__ __forceinline__ void ldsm4t(uint32_t& r0, uint32_t& r1, uint32_t& r2, uint32_t& r3,
                                       uint32_t saddr)
{
    asm volatile("ldmatrix.sync.aligned.m8n8.x4.trans.shared.b16 {%0,%1,%2,%3}, [%4];"
                 : "=r"(r0), "=r"(r1), "=r"(r2), "=r"(r3) : "r"(saddr));
}

#define CP16(dst, src) \
    asm volatile("cp.async.cg.shared.global [%0], [%1], 16;" :: "r"(dst), "l"(src))
#define CP_COMMIT() asm volatile("cp.async.commit_group;" ::: "memory")
#define CP_WAIT0()  asm volatile("cp.async.wait_group 0;" ::: "memory")

__device__ __forceinline__ uint32_t pack_h2(float x0, float x1)
{
    __half2 h = __floats2half2_rn(x0, x1);
    return *reinterpret_cast<uint32_t*>(&h);
}
__device__ __forceinline__ float ex2f(float x)
{
    float y;
    asm("ex2.approx.ftz.f32 %0, %1;" : "=f"(y) : "f"(x));
    return y;
}

// one-time K/V conversion: fp32 -> single fp16 plane each
__global__ __launch_bounds__(256)
void conv_kv(const float4* __restrict__ k, const float4* __restrict__ v)
{
    int i = blockIdx.x * blockDim.x + threadIdx.x;
    if (i >= N4PLANE) return;
    float4 x = k[i];
    g_kh[i] = make_uint2(pack_h2(x.x, x.y), pack_h2(x.z, x.w));
    float4 y = v[i];
    g_vh[i] = make_uint2(pack_h2(y.x, y.y), pack_h2(y.z, y.w));
}

// one-time mask packing: 64 int32 -> 64 bits (uint2) per (b,row,ktile)
__global__ __launch_bounds__(256)
void conv_mask(const int* __restrict__ mask)
{
    int t = blockIdx.x * blockDim.x + threadIdx.x;
    if (t >= NMB) return;
    int kb   = t & (NTILES - 1);
    int brow = t >> 5;                         // b*SSEQ + row
    const int4* src = (const int4*)(mask + (size_t)brow * SSEQ + kb * BN);
    uint32_t lo = 0, hi = 0;
    #pragma unroll
    for (int i = 0; i < 8; i++) {
        int4 m = src[i];
        uint32_t bits = (m.x ? 1u : 0u) | (m.y ? 2u : 0u) | (m.z ? 4u : 0u) | (m.w ? 8u : 0u);
        lo |= bits << (i * 4);
    }
    #pragma unroll
    for (int i = 8; i < 16; i++) {
        int4 m = src[i];
        uint32_t bits = (m.x ? 1u : 0u) | (m.y ? 2u : 0u) | (m.z ? 4u : 0u) | (m.w ? 8u : 0u);
        hi |= bits << (i * 4 - 32);
    }
    g_mb[t] = make_uint2(lo, hi);
}

// async-stage K tile: 4 cp.async/thread
__device__ __forceinline__ void cp_tile_k(uint32_t sb, int dstbuf, size_t base_e, int tid)
{
    #pragma unroll
    for (int i = 0; i < 4; i++) {
        int chunk = i * NTH + tid;
        int row = chunk >> 4, c = chunk & 15;
        uint32_t smoff = (uint32_t)(row * 272 + c * 16);
        size_t gb = (base_e + (size_t)row * DDIM + c * 8) * 2;
        CP16(sb + KBUF_W(dstbuf) * 4 + smoff, (const char*)g_kh + gb);
    }
}
// async-stage V tile: 4 cp.async/thread (3-deep ring)
__device__ __forceinline__ void cp_tile_v(uint32_t sb, int dstbuf, size_t base_e, int tid)
{
    #pragma unroll
    for (int i = 0; i < 4; i++) {
        int chunk = i * NTH + tid;
        int row = chunk >> 4, c = chunk & 15;
        uint32_t smoff = (uint32_t)(row * 272 + c * 16);
        size_t gb = (base_e + (size_t)row * DDIM + c * 8) * 2;
        CP16(sb + VBUF_W(dstbuf) * 4 + smoff, (const char*)g_vh + gb);
    }
}

// score GEMM for one 64-key tile: sc[16 rows][64 keys], Q fragments in registers
__device__ __forceinline__ void score_mma(float (&sc)[8][4], uint32_t k_ad,
                                          const uint32_t (&qh)[8][4])
{
    #pragma unroll
    for (int j = 0; j < 8; j++)
        #pragma unroll
        for (int p = 0; p < 4; p++) sc[j][p] = 0.f;
    #pragma unroll
    for (int ks = 0; ks < 8; ks++) {
        uint32_t bf[4][4];
        #pragma unroll
        for (int jp = 0; jp < 4; jp++)
            ldsm4(bf[jp][0], bf[jp][1], bf[jp][2], bf[jp][3],
                  k_ad + ks * 32 + jp * (16 * QST * 2));
        #pragma unroll
        for (int jp = 0; jp < 4; jp++) {
            mma_f16(sc[2 * jp],     qh[ks][0], qh[ks][1], qh[ks][2], qh[ks][3],
                    bf[jp][0], bf[jp][1]);
            mma_f16(sc[2 * jp + 1], qh[ks][0], qh[ks][1], qh[ks][2], qh[ks][3],
                    bf[jp][2], bf[jp][3]);
        }
    }
}

// phase-A epilogue: masked exp (scores pre-scaled by scale*log2e) -> rowsums
__device__ __forceinline__ void epiA(const float (&sc)[8][4], uint2 mb0, uint2 mb1,
                                     int tg, float& rs0, float& rs1)
{
    #pragma unroll
    for (int j = 0; j < 8; j++) {
        uint32_t w0 = (j < 4) ? mb0.x : mb0.y;
        uint32_t w1 = (j < 4) ? mb1.x : mb1.y;
        int sh = tg * 2 + (j & 3) * 8;
        float e00 = ((w0 >> sh) & 1)       ? ex2f(sc[j][0]) : 0.f;
        float e01 = ((w0 >> (sh + 1)) & 1) ? ex2f(sc[j][1]) : 0.f;
        float e10 = ((w1 >> sh) & 1)       ? ex2f(sc[j][2]) : 0.f;
        float e11 = ((w1 >> (sh + 1)) & 1) ? ex2f(sc[j][3]) : 0.f;
        rs0 += e00 + e01;
        rs1 += e10 + e11;
    }
}

// phase-B epilogue: masked exp, normalized attn store, pack e (fp16)
__device__ __forceinline__ void epiB(const float (&sc)[8][4], uint2 mb0, uint2 mb1,
                                     int tg, int cbase, float inv0, float inv1,
                                     float* a0p, float* a1p, uint32_t (&eh)[16])
{
    #pragma unroll
    for (int j = 0; j < 8; j++) {
        const int c = cbase + tg * 2 + j * 8;
        uint32_t w0 = (j < 4) ? mb0.x : mb0.y;
        uint32_t w1 = (j < 4) ? mb1.x : mb1.y;
        int sh = tg * 2 + (j & 3) * 8;
        float e00 = ((w0 >> sh) & 1)       ? ex2f(sc[j][0]) : 0.f;
        float e01 = ((w0 >> (sh + 1)) & 1) ? ex2f(sc[j][1]) : 0.f;
        float e10 = ((w1 >> sh) & 1)       ? ex2f(sc[j][2]) : 0.f;
        float e11 = ((w1 >> (sh + 1)) & 1) ? ex2f(sc[j][3]) : 0.f;
        *(float2*)(a0p + c) = make_float2(e00 * inv0, e01 * inv0);
        *(float2*)(a1p + c) = make_float2(e10 * inv1, e11 * inv1);
        eh[j * 2]     = pack_h2(e00, e01);
        eh[j * 2 + 1] = pack_h2(e10, e11);
    }
}

// PV GEMM: o[16 rows][128 d] += e[16x64] * V[64x128]
__device__ __forceinline__ void pv_mma(float (&o)[16][4], const uint32_t (&eh)[16],
                                       uint32_t v_ad)
{
    #pragma unroll
    for (int ks = 0; ks < 4; ks++) {
        uint32_t a0 = eh[ks * 4 + 0], a1 = eh[ks * 4 + 1];
        uint32_t a2 = eh[ks * 4 + 2], a3 = eh[ks * 4 + 3];
        #pragma unroll
        for (int gjn = 0; gjn < 2; gjn++) {
            uint32_t vf[4][4];
            #pragma unroll
            for (int j = 0; j < 4; j++) {
                int jnp = gjn * 4 + j;
                ldsm4t(vf[j][0], vf[j][1], vf[j][2], vf[j][3],
                       v_ad + ks * (16 * QST * 2) + jnp * 32);
            }
            #pragma unroll
            for (int j = 0; j < 4; j++) {
                int jnp = gjn * 4 + j;
                mma_f16(o[2 * jnp],     a0, a1, a2, a3, vf[j][0], vf[j][1]);
                mma_f16(o[2 * jnp + 1], a0, a1, a2, a3, vf[j][2], vf[j][3]);
            }
        }
    }
}

__global__ __launch_bounds__(NTH, 1)
void attn_mma(const float* __restrict__ q,
              float* __restrict__ out,
              float* __restrict__ attn)
{
    extern __shared__ uint32_t SW[];
    const uint32_t sb = smem_u32(SW);

    const int tid  = threadIdx.x;
    const int lane = tid & 31;
    const int w16  = (tid >> 5) * 16;
    const int g    = lane >> 2;
    const int tg   = lane & 3;

    const int h      = blockIdx.x;
    const int qblock = blockIdx.y;
    const int b      = blockIdx.z;
    const int bh     = b * HH + h;
    const int q0     = qblock * BM;
    const size_t head = (size_t)bh * SSEQ * DDIM;

    // ---- async-stage K tile 0 ----
    cp_tile_k(sb, 0, head, tid);
    CP_COMMIT();

    // ---- stage Q tile (128x128), pre-scaled by scale*log2e, single fp16 plane ----
    {
        const float qsc = 0.08838834764831843f * 1.4426950408889634f;
        const float4* qp4 = (const float4*)(q + head + (size_t)q0 * DDIM);
        #pragma unroll
        for (int it = 0; it < 16; it++) {
            int idx = it * NTH + tid;
            int row = idx >> 5;
            int c4  = (idx & 31) << 2;
            float4 x = qp4[idx];
            int w = (row * QST + c4) >> 1;
            *(uint2*)(SW + Q_HI_W + w) =
                make_uint2(pack_h2(x.x * qsc, x.y * qsc), pack_h2(x.z * qsc, x.w * qsc));
        }
    }

    // ldmatrix lane-address bases (byte offsets within a tile)
    const uint32_t a_byte  = (uint32_t)(((w16 + (lane & 15)) * QST + ((lane & 16) ? 8 : 0)) * 2);
    const uint32_t qhi_ad  = sb + Q_HI_W * 4 + a_byte;
    const uint32_t bk_byte = (uint32_t)((((lane & 7) + ((lane & 16) ? 8 : 0)) * QST +
                                         ((lane & 8) ? 8 : 0)) * 2);
    const uint32_t bv_byte = (uint32_t)((((lane & 7) + ((lane & 8) ? 8 : 0)) * QST) * 2 +
                                        ((lane & 16) ? 16 : 0));

    const int r0 = q0 + w16 + g;
    const uint2* mbp = g_mb + ((size_t)b * SSEQ + r0) * NTILES;
    float* a0p = attn + ((size_t)bh * SSEQ + r0) * SSEQ;
    float* a1p = a0p + (size_t)8 * SSEQ;

    float rsum0 = 0.f, rsum1 = 0.f;
    float scA[8][4], scB[8][4];

    CP_WAIT0();
    __syncthreads();

    // ---- hoist loop-invariant Q A-fragments ----
    uint32_t qh[8][4];
    #pragma unroll
    for (int ks = 0; ks < 8; ks++)
        ldsm4(qh[ks][0], qh[ks][1], qh[ks][2], qh[ks][3], qhi_ad + ks * 32);

    // ================= PHASE A: rowsums, epilogue pipelined 1 tile behind =========
    // peel tile 0
    cp_tile_k(sb, 1, head + (size_t)BN * DDIM, tid);
    CP_COMMIT();
    uint2 pm0 = mbp[0], pm1 = mbp[8 * NTILES];
    score_mma(scA, sb + KBUF_W(0) * 4 + bk_byte, qh);

    for (int kb = 1; kb + 1 < NTILES; kb += 2) {
        // step: score(kb)->scB, epi(kb-1)=scA
        CP_WAIT0();
        __syncthreads();
        cp_tile_k(sb, (kb + 1) & 1, head + (size_t)(kb + 1) * BN * DDIM, tid);
        CP_COMMIT();
        uint2 nm0 = mbp[kb], nm1 = mbp[8 * NTILES + kb];
        score_mma(scB, sb + KBUF_W(kb & 1) * 4 + bk_byte, qh);
        epiA(scA, pm0, pm1, tg, rsum0, rsum1);
        pm0 = nm0; pm1 = nm1;

        // step: score(kb+1)->scA, epi(kb)=scB
        CP_WAIT0();
        __syncthreads();
        if (kb + 2 < NTILES) {
            cp_tile_k(sb, (kb + 2) & 1, head + (size_t)(kb + 2) * BN * DDIM, tid);
            CP_COMMIT();
        }
        nm0 = mbp[kb + 1]; nm1 = mbp[8 * NTILES + kb + 1];
        score_mma(scA, sb + KBUF_W((kb + 1) & 1) * 4 + bk_byte, qh);
        epiA(scB, pm0, pm1, tg, rsum0, rsum1);
        pm0 = nm0; pm1 = nm1;
    }
    // final: score(31)->scB, epi(30)=scA, epi(31)=scB
    CP_WAIT0();
    __syncthreads();
    {
        uint2 nm0 = mbp[NTILES - 1], nm1 = mbp[8 * NTILES + NTILES - 1];
        score_mma(scB, sb + KBUF_W((NTILES - 1) & 1) * 4 + bk_byte, qh);
        epiA(scA, pm0, pm1, tg, rsum0, rsum1);
        epiA(scB, nm0, nm1, tg, rsum0, rsum1);
    }

    // rowsum butterfly -> inv in registers
    rsum0 += __shfl_xor_sync(0xFFFFFFFF, rsum0, 1);
    rsum0 += __shfl_xor_sync(0xFFFFFFFF, rsum0, 2);
    rsum1 += __shfl_xor_sync(0xFFFFFFFF, rsum1, 1);
    rsum1 += __shfl_xor_sync(0xFFFFFFFF, rsum1, 2);
    const float inv0 = 1.0f / rsum0;
    const float inv1 = 1.0f / rsum1;

    // ================= PHASE B: normalized attn + PV, pipelined =================
    float o[16][4];
    #pragma unroll
    for (int jn = 0; jn < 16; jn++)
        #pragma unroll
        for (int p = 0; p < 4; p++) o[jn][p] = 0.f;

    __syncthreads();                 // phase A readers done before re-staging bufs
    cp_tile_k(sb, 0, head, tid);
    cp_tile_v(sb, 0, head, tid);
    CP_COMMIT();
    CP_WAIT0();
    __syncthreads();

    // peel tile 0
    cp_tile_k(sb, 1, head + (size_t)BN * DDIM, tid);
    cp_tile_v(sb, 1, head + (size_t)BN * DDIM, tid);
    CP_COMMIT();
    pm0 = mbp[0]; pm1 = mbp[8 * NTILES];
    score_mma(scA, sb + KBUF_W(0) * 4 + bk_byte, qh);

    for (int kb = 1; kb + 1 < NTILES; kb += 2) {
        // step: score(kb)->scB, epi+PV(kb-1)=scA
        CP_WAIT0();
        __syncthreads();
        cp_tile_k(sb, (kb + 1) & 1, head + (size_t)(kb + 1) * BN * DDIM, tid);
        cp_tile_v(sb, (kb + 1) % 3, head + (size_t)(kb + 1) * BN * DDIM, tid);
        CP_COMMIT();
        uint2 nm0 = mbp[kb], nm1 = mbp[8 * NTILES + kb];
        score_mma(scB, sb + KBUF_W(kb & 1) * 4 + bk_byte, qh);
        {
            uint32_t eh[16];
            epiB(scA, pm0, pm1, tg, (kb - 1) * BN, inv0, inv1, a0p, a1p, eh);
            pv_mma(o, eh, sb + VBUF_W((kb - 1) % 3) * 4 + bv_byte);
        }
        pm0 = nm0; pm1 = nm1;

        // step: score(kb+1)->scA, epi+PV(kb)=scB
        CP_WAIT0();
        __syncthreads();
        if (kb + 2 < NTILES) {
            cp_tile_k(sb, (kb + 2) & 1, head + (size_t)(kb + 2) * BN * DDIM, tid);
            cp_tile_v(sb, (kb + 2) % 3, head + (size_t)(kb + 2) * BN * DDIM, tid);
            CP_COMMIT();
        }
        nm0 = mbp[kb + 1]; nm1 = mbp[8 * NTILES + kb + 1];
        score_mma(scA, sb + KBUF_W((kb + 1) & 1) * 4 + bk_byte, qh);
        {
            uint32_t eh[16];
            epiB(scB, pm0, pm1, tg, kb * BN, inv0, inv1, a0p, a1p, eh);
            pv_mma(o, eh, sb + VBUF_W(kb % 3) * 4 + bv_byte);
        }
        pm0 = nm0; pm1 = nm1;
    }
    // final: score(31)->scB, epi+PV(30)=scA, epi+PV(31)=scB
    CP_WAIT0();
    __syncthreads();
    {
        uint2 nm0 = mbp[NTILES - 1], nm1 = mbp[8 * NTILES + NTILES - 1];
        score_mma(scB, sb + KBUF_W((NTILES - 1) & 1) * 4 + bk_byte, qh);
        uint32_t eh[16];
        epiB(scA, pm0, pm1, tg, (NTILES - 2) * BN, inv0, inv1, a0p, a1p, eh);
        pv_mma(o, eh, sb + VBUF_W((NTILES - 2) % 3) * 4 + bv_byte);
        epiB(scB, nm0, nm1, tg, (NTILES - 1) * BN, inv0, inv1, a0p, a1p, eh);
        pv_mma(o, eh, sb + VBUF_W((NTILES - 1) % 3) * 4 + bv_byte);
    }

    // ---- normalized out ----
    float* o0p = out + ((size_t)bh * SSEQ + r0) * DDIM;
    float* o1p = o0p + (size_t)8 * DDIM;
    #pragma unroll
    for (int jn = 0; jn < 16; jn++) {
        const int c = jn * 8 + tg * 2;
        *(float2*)(o0p + c) = make_float2(o[jn][0] * inv0, o[jn][1] * inv0);
        *(float2*)(o1p + c) = make_float2(o[jn][2] * inv1, o[jn][3] * inv1);
    }
}

extern "C" void kernel_launch(void* const* d_in, const int* in_sizes, int n_in,
                              void* d_out, int out_size)
{
    const float* q    = (const float*)d_in[0];
    const float* k    = (const float*)d_in[1];
    const float* v    = (const float*)d_in[2];
    const int*   mask = (const int*)d_in[3];

    float* out  = (float*)d_out;
    float* attn = out + (size_t)BB * HH * SSEQ * DDIM;

    // one-time (per launch) precompute: K/V fp16 planes + packed mask bits
    conv_kv<<<N4PLANE / 256, 256>>>((const float4*)k, (const float4*)v);
    conv_mask<<<NMB / 256, 256>>>(mask);

    cudaFuncSetAttribute(attn_mma, cudaFuncAttributeMaxDynamicSharedMemorySize, SMEM_BYTES);
    dim3 grid(HH, SSEQ / BM, BB);       // h fastest: concurrent CTAs share K/V + mask in L2
    attn_mma<<<grid, NTH, SMEM_BYTES>>>(q, out, attn);
}